// round 11
// baseline (speedup 1.0000x reference)
#include <cuda_runtime.h>
#include <cuda_bf16.h>
#include <math.h>
#include <stdint.h>

#define D 128
#define DD (128 * 128)
#define EMAX 640000
#define NN 20000
#define EPS 1e-5f

// pitch-272 bf16 images (128 bf16 + 8 pad) -> conflict-free fragment LDS
#define PITCH 272
#define IMG (128 * PITCH)            // 34816 B per image
#define WIMG (2 * IMG)               // packed weight hi+lo: 69632 B
#define GEMM_SMEM (4 * IMG)          // single-layer: A hi/lo + W hi/lo
#define FUSED_SMEM (6 * IMG)         // fused: A hi/lo + W1 hi/lo + W2 hi/lo = 208896
#define GRID 148

// ---------------- scratch (device globals; no allocation allowed) -------------
__device__ float g_bufA[(size_t)EMAX * D];
__device__ float g_bufB[(size_t)EMAX * D];
__device__ float g_bufC[(size_t)EMAX * D];
__device__ float g_agg[NN * D];
__device__ float g_deg[NN];
__device__ float g_a2[NN * D];
__device__ float g_a3[NN * D];
__device__ float g_hn[NN * D];
__device__ float g_P[NN * D];
__device__ float g_Q[NN * D];
__device__ float g_Wf[DD];
__device__ float g_bf[D];
__device__ float g_sums[5 * D];
__device__ float g_sumsq[5 * D];
__device__ float g_bnS[5 * D];
__device__ float g_bnT[5 * D];
__device__ char g_wp[12 * WIMG];     // 12 packed weight images

__device__ __forceinline__ float elu1(float x) { return x > 0.f ? x : expm1f(x); }

__device__ __forceinline__ uint32_t s2u(const void* p) {
    uint32_t a;
    asm("{ .reg .u64 t; cvta.to.shared.u64 t, %1; cvt.u32.u64 %0, t; }"
        : "=r"(a) : "l"(p));
    return a;
}
__device__ __forceinline__ uint32_t lds32(uint32_t addr) {
    uint32_t v;
    asm volatile("ld.shared.b32 %0, [%1];" : "=r"(v) : "r"(addr));
    return v;
}
__device__ __forceinline__ void mma_bf16(float* c, const uint32_t* a, const uint32_t* b) {
    asm volatile(
        "mma.sync.aligned.m16n8k16.row.col.f32.bf16.bf16.f32 "
        "{%0,%1,%2,%3}, {%4,%5,%6,%7}, {%8,%9}, {%0,%1,%2,%3};"
        : "+f"(c[0]), "+f"(c[1]), "+f"(c[2]), "+f"(c[3])
        : "r"(a[0]), "r"(a[1]), "r"(a[2]), "r"(a[3]), "r"(b[0]), "r"(b[1]));
}
__device__ __forceinline__ void split2(float a, float b, uint32_t& h, uint32_t& l) {
    __nv_bfloat16 ha = __float2bfloat16_rn(a), hb = __float2bfloat16_rn(b);
    float ra = a - __bfloat162float(ha), rb = b - __bfloat162float(hb);
    __nv_bfloat16 la = __float2bfloat16_rn(ra), lb = __float2bfloat16_rn(rb);
    h = ((uint32_t)__bfloat16_as_ushort(hb) << 16) | __bfloat16_as_ushort(ha);
    l = ((uint32_t)__bfloat16_as_ushort(lb) << 16) | __bfloat16_as_ushort(la);
}

// Pack W[128k,128n] row-major fp32 -> transposed [n][k] bf16 hi/lo images.
__global__ void pack_w(const float* __restrict__ W, char* __restrict__ dst) {
    int i = blockIdx.x * 256 + threadIdx.x;
    if (i >= 16384) return;
    int n = i >> 7, k = i & 127;
    float x = W[k * 128 + n];
    __nv_bfloat16 h = __float2bfloat16_rn(x);
    __nv_bfloat16 l = __float2bfloat16_rn(x - __bfloat162float(h));
    *(__nv_bfloat16*)(dst + n * PITCH + k * 2) = h;
    *(__nv_bfloat16*)(dst + IMG + n * PITCH + k * 2) = l;
}

// 3-pass (hh + hl + lh) bf16 mainloop. A images at sb/sb+IMG; W at wb/wb+IMG.
__device__ __forceinline__ void mainloop3(uint32_t sb, uint32_t wb,
                                          int mrow, int ncol, int g, int q,
                                          float acc[2][8][4])
{
#pragma unroll
    for (int mt = 0; mt < 2; ++mt)
#pragma unroll
        for (int nt = 0; nt < 8; ++nt)
#pragma unroll
            for (int c = 0; c < 4; ++c) acc[mt][nt][c] = 0.f;

#pragma unroll
    for (int k0 = 0; k0 < 128; k0 += 16) {
        uint32_t ah[2][4], al[2][4];
#pragma unroll
        for (int mt = 0; mt < 2; ++mt) {
            uint32_t base = sb + (mrow + mt * 16 + g) * PITCH + (k0 + 2 * q) * 2;
            ah[mt][0] = lds32(base);
            ah[mt][1] = lds32(base + 8 * PITCH);
            ah[mt][2] = lds32(base + 16);
            ah[mt][3] = lds32(base + 8 * PITCH + 16);
            al[mt][0] = lds32(base + IMG);
            al[mt][1] = lds32(base + IMG + 8 * PITCH);
            al[mt][2] = lds32(base + IMG + 16);
            al[mt][3] = lds32(base + IMG + 8 * PITCH + 16);
        }
        uint32_t bh[8][2], bl[8][2];
#pragma unroll
        for (int nt = 0; nt < 8; ++nt) {
            uint32_t base = wb + (ncol + nt * 8 + g) * PITCH + (k0 + 2 * q) * 2;
            bh[nt][0] = lds32(base);
            bh[nt][1] = lds32(base + 16);
            bl[nt][0] = lds32(base + IMG);
            bl[nt][1] = lds32(base + IMG + 16);
        }
#pragma unroll
        for (int mt = 0; mt < 2; ++mt)
#pragma unroll
            for (int nt = 0; nt < 8; ++nt)
                mma_bf16(acc[mt][nt], ah[mt], bh[nt]);
#pragma unroll
        for (int mt = 0; mt < 2; ++mt)
#pragma unroll
            for (int nt = 0; nt < 8; ++nt)
                mma_bf16(acc[mt][nt], ah[mt], bl[nt]);
#pragma unroll
        for (int mt = 0; mt < 2; ++mt)
#pragma unroll
            for (int nt = 0; nt < 8; ++nt)
                mma_bf16(acc[mt][nt], al[mt], bh[nt]);
    }
}

// stats: shfl-bfly reduce over g (lane bits 2..4), then global atomics from g==0
__device__ __forceinline__ void stats_flush(int sidx, int ncol, int g, int q,
                                            float st_s[8][2], float st_q[8][2])
{
#pragma unroll
    for (int nt = 0; nt < 8; ++nt)
#pragma unroll
        for (int p = 0; p < 2; ++p) {
            float s = st_s[nt][p], qq = st_q[nt][p];
            s += __shfl_xor_sync(0xffffffffu, s, 4);
            s += __shfl_xor_sync(0xffffffffu, s, 8);
            s += __shfl_xor_sync(0xffffffffu, s, 16);
            qq += __shfl_xor_sync(0xffffffffu, qq, 4);
            qq += __shfl_xor_sync(0xffffffffu, qq, 8);
            qq += __shfl_xor_sync(0xffffffffu, qq, 16);
            if (g == 0) {
                int col = ncol + nt * 8 + 2 * q + p;
                atomicAdd(&g_sums[sidx * 128 + col], s);
                atomicAdd(&g_sumsq[sidx * 128 + col], qq);
            }
        }
}

// ---------- fused 2-layer MLP: C = elu(elu(A@W1+b1)@W2+b2), optional stats ----
// Persistent, grid=148. W1/W2 in smem once per block; intermediate stays smem.
template <int STATS>
__global__ void __launch_bounds__(256, 1) fused2_mma(
    const float* __restrict__ A,
    const char* __restrict__ Wp1, const float* __restrict__ b1,
    const char* __restrict__ Wp2, const float* __restrict__ b2,
    float* __restrict__ C, int M, int T)
{
    extern __shared__ char smem[];
    const int tid = threadIdx.x;

    {   // copy both packed weights once per block
        const float4* w1 = (const float4*)Wp1;
        const float4* w2 = (const float4*)Wp2;
        float4* d1 = (float4*)(smem + 2 * IMG);
        float4* d2 = (float4*)(smem + 4 * IMG);
#pragma unroll
        for (int j = 0; j < 17; ++j) {
            int idx = tid + 256 * j;
            if (idx < WIMG / 16) { d1[idx] = w1[idx]; d2[idx] = w2[idx]; }
        }
    }

    const int wid = tid >> 5, lane = tid & 31;
    const int wm = wid >> 1, wn = wid & 1;
    const int g = lane >> 2, q = lane & 3;
    const uint32_t sb = s2u(smem);
    const int mrow = wm * 32;
    const int ncol = wn * 64;

    float st_s[8][2], st_q[8][2];
    if (STATS >= 0) {
#pragma unroll
        for (int nt = 0; nt < 8; ++nt) {
            st_s[nt][0] = st_s[nt][1] = 0.f;
            st_q[nt][0] = st_q[nt][1] = 0.f;
        }
    }

    for (int t = blockIdx.x; t < T; t += GRID) {
        const int row0 = t * 128;
        // ---- load + split A tile ----
        {
            float4 tmp[16];
#pragma unroll
            for (int j = 0; j < 16; ++j) {
                int idx = tid + 256 * j;
                int r = idx >> 5, c4 = idx & 31;
                tmp[j] = (row0 + r < M)
                    ? reinterpret_cast<const float4*>(A)[(size_t)(row0 + r) * 32 + c4]
                    : make_float4(0.f, 0.f, 0.f, 0.f);
            }
#pragma unroll
            for (int j = 0; j < 16; ++j) {
                int idx = tid + 256 * j;
                int r = idx >> 5, c4 = idx & 31;
                uint32_t h0, l0, h1, l1;
                split2(tmp[j].x, tmp[j].y, h0, l0);
                split2(tmp[j].z, tmp[j].w, h1, l1);
                *(uint2*)(smem + r * PITCH + c4 * 8) = make_uint2(h0, h1);
                *(uint2*)(smem + IMG + r * PITCH + c4 * 8) = make_uint2(l0, l1);
            }
        }
        __syncthreads();

        float acc[2][8][4];
        mainloop3(sb, sb + 2 * IMG, mrow, ncol, g, q, acc);   // fc1
        __syncthreads();   // all reads of A images done before overwrite

        // ---- bias + elu + split intermediate back into A images ----
#pragma unroll
        for (int mt = 0; mt < 2; ++mt) {
            int rl = mrow + mt * 16 + g;
#pragma unroll
            for (int nt = 0; nt < 8; ++nt) {
                int col = ncol + nt * 8 + 2 * q;
                float c0 = __ldg(b1 + col), c1 = __ldg(b1 + col + 1);
                float x0 = elu1(acc[mt][nt][0] + c0), x1 = elu1(acc[mt][nt][1] + c1);
                float x2 = elu1(acc[mt][nt][2] + c0), x3 = elu1(acc[mt][nt][3] + c1);
                uint32_t h, l;
                split2(x0, x1, h, l);
                *(uint32_t*)(smem + rl * PITCH + col * 2) = h;
                *(uint32_t*)(smem + IMG + rl * PITCH + col * 2) = l;
                split2(x2, x3, h, l);
                *(uint32_t*)(smem + (rl + 8) * PITCH + col * 2) = h;
                *(uint32_t*)(smem + IMG + (rl + 8) * PITCH + col * 2) = l;
            }
        }
        __syncthreads();

        mainloop3(sb, sb + 4 * IMG, mrow, ncol, g, q, acc);   // fc2

        // ---- epilogue: bias + elu + store + stats ----
#pragma unroll
        for (int mt = 0; mt < 2; ++mt) {
            int r = row0 + mrow + mt * 16 + g;
#pragma unroll
            for (int nt = 0; nt < 8; ++nt) {
                int col = ncol + nt * 8 + 2 * q;
                float c0 = __ldg(b2 + col), c1 = __ldg(b2 + col + 1);
                float x0 = elu1(acc[mt][nt][0] + c0), x1 = elu1(acc[mt][nt][1] + c1);
                float x2 = elu1(acc[mt][nt][2] + c0), x3 = elu1(acc[mt][nt][3] + c1);
                if (r < M) {
                    float2 o; o.x = x0; o.y = x1;
                    *reinterpret_cast<float2*>(&C[(size_t)r * 128 + col]) = o;
                    if (STATS >= 0) {
                        st_s[nt][0] += x0; st_q[nt][0] += x0 * x0;
                        st_s[nt][1] += x1; st_q[nt][1] += x1 * x1;
                    }
                }
                if (r + 8 < M) {
                    float2 o; o.x = x2; o.y = x3;
                    *reinterpret_cast<float2*>(&C[(size_t)(r + 8) * 128 + col]) = o;
                    if (STATS >= 0) {
                        st_s[nt][0] += x2; st_q[nt][0] += x2 * x2;
                        st_s[nt][1] += x3; st_q[nt][1] += x3 * x3;
                    }
                }
            }
        }
        __syncthreads();   // A images free for next tile
    }
    if (STATS >= 0) stats_flush(STATS, ncol, g, q, st_s, st_q);
}

// ---------- single-layer GEMM (R10 path) + optional gather prologue/stats -----
// GATHER=1: A-tile built as elu(pre + P[src] + Q[dst] + eb1) before the GEMM.
template <int ACT, int STATS, int GATHER>
__global__ void __launch_bounds__(256, 1) gemm_mma(
    const float* __restrict__ A, const char* __restrict__ Wp,
    const float* __restrict__ bias, float* __restrict__ C, int M, int T,
    const int* __restrict__ src, const int* __restrict__ dst,
    const float* __restrict__ eb1)
{
    extern __shared__ char smem[];
    const int tid = threadIdx.x;

    {
        const float4* ws = (const float4*)Wp;
        float4* wd = (float4*)(smem + 2 * IMG);
#pragma unroll
        for (int j = 0; j < 17; ++j) {
            int idx = tid + 256 * j;
            if (idx < WIMG / 16) wd[idx] = ws[idx];
        }
    }

    const int wid = tid >> 5, lane = tid & 31;
    const int wm = wid >> 1, wn = wid & 1;
    const int g = lane >> 2, q = lane & 3;
    const uint32_t sb = s2u(smem);
    const int mrow = wm * 32;
    const int ncol = wn * 64;

    float st_s[8][2], st_q[8][2];
    if (STATS >= 0) {
#pragma unroll
        for (int nt = 0; nt < 8; ++nt) {
            st_s[nt][0] = st_s[nt][1] = 0.f;
            st_q[nt][0] = st_q[nt][1] = 0.f;
        }
    }

    for (int t = blockIdx.x; t < T; t += GRID) {
        const int row0 = t * 128;
        {
            float4 tmp[16];
#pragma unroll
            for (int j = 0; j < 16; ++j) {
                int idx = tid + 256 * j;
                int r = idx >> 5, c4 = idx & 31;
                float4 v = make_float4(0.f, 0.f, 0.f, 0.f);
                if (row0 + r < M) {
                    v = reinterpret_cast<const float4*>(A)[(size_t)(row0 + r) * 32 + c4];
                    if (GATHER) {
                        int s = __ldg(src + row0 + r);
                        int d = __ldg(dst + row0 + r);
                        float4 p = reinterpret_cast<const float4*>(g_P)[(size_t)s * 32 + c4];
                        float4 qv = reinterpret_cast<const float4*>(g_Q)[(size_t)d * 32 + c4];
                        float4 bb = reinterpret_cast<const float4*>(eb1)[c4];
                        v.x = elu1(v.x + p.x + qv.x + bb.x);
                        v.y = elu1(v.y + p.y + qv.y + bb.y);
                        v.z = elu1(v.z + p.z + qv.z + bb.z);
                        v.w = elu1(v.w + p.w + qv.w + bb.w);
                    }
                }
                tmp[j] = v;
            }
#pragma unroll
            for (int j = 0; j < 16; ++j) {
                int idx = tid + 256 * j;
                int r = idx >> 5, c4 = idx & 31;
                uint32_t h0, l0, h1, l1;
                split2(tmp[j].x, tmp[j].y, h0, l0);
                split2(tmp[j].z, tmp[j].w, h1, l1);
                *(uint2*)(smem + r * PITCH + c4 * 8) = make_uint2(h0, h1);
                *(uint2*)(smem + IMG + r * PITCH + c4 * 8) = make_uint2(l0, l1);
            }
        }
        __syncthreads();

        float acc[2][8][4];
        mainloop3(sb, sb + 2 * IMG, mrow, ncol, g, q, acc);

#pragma unroll
        for (int mt = 0; mt < 2; ++mt) {
            int r = row0 + mrow + mt * 16 + g;
#pragma unroll
            for (int nt = 0; nt < 8; ++nt) {
                int col = ncol + nt * 8 + 2 * q;
                float c0 = bias ? __ldg(bias + col) : 0.f;
                float c1 = bias ? __ldg(bias + col + 1) : 0.f;
                float x0 = acc[mt][nt][0] + c0, x1 = acc[mt][nt][1] + c1;
                float x2 = acc[mt][nt][2] + c0, x3 = acc[mt][nt][3] + c1;
                if (ACT) { x0 = elu1(x0); x1 = elu1(x1); x2 = elu1(x2); x3 = elu1(x3); }
                if (r < M) {
                    float2 o; o.x = x0; o.y = x1;
                    *reinterpret_cast<float2*>(&C[(size_t)r * 128 + col]) = o;
                    if (STATS >= 0) {
                        st_s[nt][0] += x0; st_q[nt][0] += x0 * x0;
                        st_s[nt][1] += x1; st_q[nt][1] += x1 * x1;
                    }
                }
                if (r + 8 < M) {
                    float2 o; o.x = x2; o.y = x3;
                    *reinterpret_cast<float2*>(&C[(size_t)(r + 8) * 128 + col]) = o;
                    if (STATS >= 0) {
                        st_s[nt][0] += x2; st_q[nt][0] += x2 * x2;
                        st_s[nt][1] += x3; st_q[nt][1] += x3 * x3;
                    }
                }
            }
        }
        __syncthreads();
    }
    if (STATS >= 0) stats_flush(STATS, ncol, g, q, st_s, st_q);
}

__global__ void finalize_bn(int sidx, float invM, const float* __restrict__ g,
                            const float* __restrict__ bt)
{
    int c = threadIdx.x;
    float mu = g_sums[sidx * 128 + c] * invM;
    float var = fmaxf(g_sumsq[sidx * 128 + c] * invM - mu * mu, 0.f);
    float s = g[c] * rsqrtf(var + EPS);
    g_bnS[sidx * 128 + c] = s;
    g_bnT[sidx * 128 + c] = bt[c] - mu * s;
}

// Fold per-column input affine (x*s + t) of BN sidx into next layer weights.
__global__ void fold_bn(const float* __restrict__ W, const float* __restrict__ b,
                        int sidx)
{
    int j = threadIdx.x;
    float acc = b[j];
    for (int k = 0; k < 128; ++k) {
        float s = g_bnS[sidx * 128 + k];
        float t = g_bnT[sidx * 128 + k];
        float w = W[k * 128 + j];
        g_Wf[k * 128 + j] = s * w;
        acc += t * w;
    }
    g_bf[j] = acc;
}

// h_e = BN0(h0) + BN1(h1); scatter-add into agg[dst], count deg[dst].
__global__ void __launch_bounds__(256) combine_scatter(
    const float* __restrict__ h0, const float* __restrict__ h1,
    const int* __restrict__ dst, int E)
{
    int e = blockIdx.x * 8 + (threadIdx.x >> 5);
    if (e >= E) return;
    int lane = threadIdx.x & 31;
    int c = lane * 4;
    float4 a = *reinterpret_cast<const float4*>(&h0[(size_t)e * 128 + c]);
    float4 b = *reinterpret_cast<const float4*>(&h1[(size_t)e * 128 + c]);
    float4 v;
    v.x = g_bnS[c + 0] * a.x + g_bnT[c + 0] + g_bnS[128 + c + 0] * b.x + g_bnT[128 + c + 0];
    v.y = g_bnS[c + 1] * a.y + g_bnT[c + 1] + g_bnS[128 + c + 1] * b.y + g_bnT[128 + c + 1];
    v.z = g_bnS[c + 2] * a.z + g_bnT[c + 2] + g_bnS[128 + c + 2] * b.z + g_bnT[128 + c + 2];
    v.w = g_bnS[c + 3] * a.w + g_bnT[c + 3] + g_bnS[128 + c + 3] * b.w + g_bnT[128 + c + 3];
    int d = dst[e];
    atomicAdd(reinterpret_cast<float4*>(&g_agg[(size_t)d * 128 + c]), v);
    if (lane == 0) atomicAdd(&g_deg[d], 1.f);
}

__global__ void divide_agg()
{
    int i = blockIdx.x * 256 + threadIdx.x;   // float4 index
    if (i >= NN * 32) return;
    int n = i >> 5;
    float inv = 1.f / fmaxf(g_deg[n], 1.f);
    float4 v = reinterpret_cast<float4*>(g_agg)[i];
    v.x *= inv; v.y *= inv; v.z *= inv; v.w *= inv;
    reinterpret_cast<float4*>(g_agg)[i] = v;
}

// h_n = BN3(a3) + BN2(a2)
__global__ void combine_node()
{
    int i = blockIdx.x * 256 + threadIdx.x;
    if (i >= NN * 128) return;
    int c = i & 127;
    g_hn[i] = g_bnS[3 * 128 + c] * g_a3[i] + g_bnT[3 * 128 + c]
            + g_bnS[2 * 128 + c] * g_a2[i] + g_bnT[2 * 128 + c];
}

// out = BN4(z)
__global__ void __launch_bounds__(256) apply_bn(float* __restrict__ out, int E)
{
    int i = blockIdx.x * 256 + threadIdx.x;   // float4 index
    if (i >= E * 32) return;
    int c = (i & 31) * 4;
    float4 v = reinterpret_cast<const float4*>(g_bufC)[i];
    float4 o;
    o.x = g_bnS[512 + c + 0] * v.x + g_bnT[512 + c + 0];
    o.y = g_bnS[512 + c + 1] * v.y + g_bnT[512 + c + 1];
    o.z = g_bnS[512 + c + 2] * v.z + g_bnT[512 + c + 2];
    o.w = g_bnS[512 + c + 3] * v.w + g_bnT[512 + c + 3];
    reinterpret_cast<float4*>(out)[i] = o;
}

__global__ void zero_scratch()
{
    int i = blockIdx.x * 256 + threadIdx.x;
    if (i < NN * 128) g_agg[i] = 0.f;
    if (i < NN) g_deg[i] = 0.f;
    if (i < 5 * 128) { g_sums[i] = 0.f; g_sumsq[i] = 0.f; }
}

// ------------------------------- launcher -------------------------------------
extern "C" void kernel_launch(void* const* d_in, const int* in_sizes, int n_in,
                              void* d_out, int out_size)
{
    const float* edata = (const float*)d_in[0];
    const int* src     = (const int*)d_in[1];
    const int* dst     = (const int*)d_in[2];
    const float* W1s = (const float*)d_in[4];
    const float* b1s = (const float*)d_in[5];
    const float* W2s = (const float*)d_in[6];
    const float* b2s = (const float*)d_in[7];
    const float* gs  = (const float*)d_in[8];
    const float* bts = (const float*)d_in[9];
    const float* eW1 = (const float*)d_in[10];
    const float* eb1 = (const float*)d_in[11];
    const float* eW2 = (const float*)d_in[12];
    const float* eb2 = (const float*)d_in[13];
    const float* eg  = (const float*)d_in[14];
    const float* ebt = (const float*)d_in[15];
    float* out = (float*)d_out;

    const int E = in_sizes[0] / 128;
    const int ET = (E + 127) / 128;
    const int NT = (NN + 127) / 128;

    cudaFuncSetAttribute(fused2_mma<0>, cudaFuncAttributeMaxDynamicSharedMemorySize, FUSED_SMEM);
    cudaFuncSetAttribute(fused2_mma<1>, cudaFuncAttributeMaxDynamicSharedMemorySize, FUSED_SMEM);
    cudaFuncSetAttribute(fused2_mma<2>, cudaFuncAttributeMaxDynamicSharedMemorySize, FUSED_SMEM);
    cudaFuncSetAttribute(fused2_mma<3>, cudaFuncAttributeMaxDynamicSharedMemorySize, FUSED_SMEM);
    cudaFuncSetAttribute((gemm_mma<0, -1, 0>), cudaFuncAttributeMaxDynamicSharedMemorySize, GEMM_SMEM);
    cudaFuncSetAttribute((gemm_mma<1, 4, 1>), cudaFuncAttributeMaxDynamicSharedMemorySize, GEMM_SMEM);

    float *bufA, *bufB, *bufC, *agg, *a2, *a3, *hn, *P, *Q, *Wf, *bf;
    char* wp;
    cudaGetSymbolAddress((void**)&bufA, g_bufA);
    cudaGetSymbolAddress((void**)&bufB, g_bufB);
    cudaGetSymbolAddress((void**)&bufC, g_bufC);
    cudaGetSymbolAddress((void**)&agg, g_agg);
    cudaGetSymbolAddress((void**)&a2, g_a2);
    cudaGetSymbolAddress((void**)&a3, g_a3);
    cudaGetSymbolAddress((void**)&hn, g_hn);
    cudaGetSymbolAddress((void**)&P, g_P);
    cudaGetSymbolAddress((void**)&Q, g_Q);
    cudaGetSymbolAddress((void**)&Wf, g_Wf);
    cudaGetSymbolAddress((void**)&bf, g_bf);
    cudaGetSymbolAddress((void**)&wp, g_wp);
    #define WP(i) (wp + (size_t)(i) * WIMG)

    zero_scratch<<<10000, 256>>>();

    // pack static weights (bf16 hi/lo, transposed [n][k] images)
    pack_w<<<64, 256>>>(W1s, WP(0));
    pack_w<<<64, 256>>>(W2s, WP(1));
    pack_w<<<64, 256>>>(W2s + DD, WP(3));
    pack_w<<<64, 256>>>(W1s + 2 * DD, WP(4));
    pack_w<<<64, 256>>>(W2s + 2 * DD, WP(5));
    pack_w<<<64, 256>>>(W2s + 3 * DD, WP(7));
    pack_w<<<64, 256>>>(eW1, WP(8));
    pack_w<<<64, 256>>>(eW1 + DD, WP(9));
    pack_w<<<64, 256>>>(eW1 + 2 * DD, WP(10));
    pack_w<<<64, 256>>>(eW2, WP(11));

    // ---- edge MLP0 (fc1+fc2 fused, stats0 fused) ----
    fused2_mma<0><<<GRID, 256, FUSED_SMEM>>>(edata, WP(0), b1s, WP(1), b2s, bufB, E, ET);
    finalize_bn<<<1, 128>>>(0, 1.f / E, gs, bts);

    // ---- edge MLP1 on BN0(h0): fold BN0 into W1s[1] ----
    fold_bn<<<1, 128>>>(W1s + DD, b1s + 128, 0);
    pack_w<<<64, 256>>>(Wf, WP(2));
    fused2_mma<1><<<GRID, 256, FUSED_SMEM>>>(bufB, WP(2), bf, WP(3), b2s + 128, bufC, E, ET);
    finalize_bn<<<1, 128>>>(1, 1.f / E, gs + 128, bts + 128);

    // ---- h_e = BN0(h0)+BN1(h1); scatter-mean over dst ----
    combine_scatter<<<(E + 7) / 8, 256>>>(bufB, bufC, dst, E);
    divide_agg<<<2500, 256>>>();

    // ---- node MLP2 (fused, stats2) ----
    fused2_mma<2><<<GRID, 256, FUSED_SMEM>>>(agg, WP(4), b1s + 256, WP(5), b2s + 256, a2, NN, NT);
    finalize_bn<<<1, 128>>>(2, 1.f / NN, gs + 256, bts + 256);

    // ---- node MLP3 on BN2(a2) (fused, stats3) ----
    fold_bn<<<1, 128>>>(W1s + 3 * DD, b1s + 384, 2);
    pack_w<<<64, 256>>>(Wf, WP(6));
    fused2_mma<3><<<GRID, 256, FUSED_SMEM>>>(a2, WP(6), bf, WP(7), b2s + 384, a3, NN, NT);
    finalize_bn<<<1, 128>>>(3, 1.f / NN, gs + 384, bts + 384);

    // ---- h_n; node-side partial products of eW1 ----
    combine_node<<<10000, 256>>>();
    gemm_mma<0, -1, 0><<<GRID, 256, GEMM_SMEM>>>(hn, WP(9), nullptr, P, NN, NT,
                                                 nullptr, nullptr, nullptr);
    gemm_mma<0, -1, 0><<<GRID, 256, GEMM_SMEM>>>(hn, WP(10), nullptr, Q, NN, NT,
                                                 nullptr, nullptr, nullptr);

    // ---- final edge MLP: pre = edata@eW1; fused gather + eW2 GEMM + stats4 ----
    gemm_mma<0, -1, 0><<<GRID, 256, GEMM_SMEM>>>(edata, WP(8), nullptr, bufA, E, ET,
                                                 nullptr, nullptr, nullptr);
    gemm_mma<1, 4, 1><<<GRID, 256, GEMM_SMEM>>>(bufA, WP(11), eb2, bufC, E, ET,
                                                src, dst, eb1);
    finalize_bn<<<1, 128>>>(4, 1.f / E, eg, ebt);
    apply_bn<<<(E * 32 + 255) / 256, 256>>>(out, E);
}